// round 15
// baseline (speedup 1.0000x reference)
#include <cuda_runtime.h>
#include <math_constants.h>

// contributions: [S=256, P=2000, C=200] fp32, row-major (c contiguous).
// Per (s, c) column along P: zero the top-4 (stable ties -> lower p), pass rest.
//
// R14: R13 refined at the DRAM wall. Block = one sample, 800 threads =
// 4 P-segments x 200 columns (ZERO idle threads, no warp straddling waste),
// PSEG=500 (R5-proven), fused in-block smem merge. Copy path uses streaming
// cache hints (__ldcs/__stcs): both streams are single-touch, keep L2 clean.
// Grid 256, 2 CTAs/SM.

static constexpr int S    = 256;
static constexpr int P    = 2000;
static constexpr int C    = 200;
static constexpr int SEG  = 4;                // P-segments per sample (in-block)
static constexpr int PSEG = P / SEG;          // 500
static constexpr int U    = 10;               // 500 = 50 * 10
static constexpr int NB   = PSEG / U;         // 50 batches
static constexpr int BLK  = SEG * C;          // 800 threads (25 warps)
static constexpr int GRID = S;                // 256 blocks

__global__ void __launch_bounds__(BLK)
numproto_topk_zero(const float* __restrict__ in, float* __restrict__ out) {
    const int tid = threadIdx.x;
    const int s   = blockIdx.x;
    const int seg = tid / C;                  // 0..3
    const int c   = tid - seg * C;            // 0..199

    __shared__ float sv[SEG][4][C];
    __shared__ int   si[SEG][4][C];

    {
        const int p0 = seg * PSEG;
        const float* __restrict__ ipp = in  + (size_t)s * P * C + (size_t)p0 * C + c;
        float*       __restrict__ opp = out + (size_t)s * P * C + (size_t)p0 * C + c;

        float t0 = -CUDART_INF_F, t1 = -CUDART_INF_F,
              t2 = -CUDART_INF_F, t3 = -CUDART_INF_F;
        int   i0 = 0, i1 = 0, i2 = 0, i3 = 0;

        int pbase = p0;
        for (int it = 0; it < NB; it++) {
            float v[U];
            #pragma unroll
            for (int u = 0; u < U; u++)
                v[u] = __ldcs(ipp + u * C);   // streaming load, immediate offsets
            #pragma unroll
            for (int u = 0; u < U; u++)
                __stcs(opp + u * C, v[u]);    // streaming store

            // batch screen: one branch per 10 elements
            float m01 = fmaxf(v[0], v[1]);
            float m23 = fmaxf(v[2], v[3]);
            float m45 = fmaxf(v[4], v[5]);
            float m67 = fmaxf(v[6], v[7]);
            float m89 = fmaxf(v[8], v[9]);
            float mx  = fmaxf(fmaxf(fmaxf(m01, m23), fmaxf(m45, m67)), m89);

            if (mx > t3) {
                #pragma unroll
                for (int u = 0; u < U; u++) {
                    float vv = v[u];
                    if (vv > t3) {            // short branchless insert
                        const int pp = pbase + u;
                        const bool c0 = vv > t0;
                        const bool c1 = vv > t1;
                        const bool c2 = vv > t2;
                        float nt0 = c0 ? vv : t0;           int ni0 = c0 ? pp : i0;
                        float nt1 = c0 ? t0 : (c1 ? vv : t1);
                        int   ni1 = c0 ? i0 : (c1 ? pp : i1);
                        float nt2 = c1 ? t1 : (c2 ? vv : t2);
                        int   ni2 = c1 ? i1 : (c2 ? pp : i2);
                        float nt3 = c2 ? t2 : vv;           int ni3 = c2 ? i2 : pp;
                        t0 = nt0; t1 = nt1; t2 = nt2; t3 = nt3;
                        i0 = ni0; i1 = ni1; i2 = ni2; i3 = ni3;
                    }
                }
            }
            ipp += U * C;
            opp += U * C;
            pbase += U;
        }

        sv[seg][0][c] = t0;  si[seg][0][c] = i0;
        sv[seg][1][c] = t1;  si[seg][1][c] = i1;
        sv[seg][2][c] = t2;  si[seg][2][c] = i2;
        sv[seg][3][c] = t3;  si[seg][3][c] = i3;
    }

    __syncthreads();   // orders this block's copy-stores before the patch

    if (tid < C) {
        float* opc = out + (size_t)s * P * C + tid;

        float m0 = -CUDART_INF_F, m1 = -CUDART_INF_F,
              m2 = -CUDART_INF_F, m3 = -CUDART_INF_F;
        int   j0 = 0x7fffffff, j1 = 0x7fffffff,
              j2 = 0x7fffffff, j3 = 0x7fffffff;

        #pragma unroll
        for (int sg = 0; sg < SEG; sg++) {
            #pragma unroll
            for (int k = 0; k < 4; k++) {
                float v = sv[sg][k][tid];
                int   i = si[sg][k][tid];
                // stable order: value desc, index asc
                if (v > m3 || (v == m3 && i < j3)) {
                    if (v > m0 || (v == m0 && i < j0)) {
                        m3 = m2; j3 = j2; m2 = m1; j2 = j1; m1 = m0; j1 = j0;
                        m0 = v;  j0 = i;
                    } else if (v > m1 || (v == m1 && i < j1)) {
                        m3 = m2; j3 = j2; m2 = m1; j2 = j1;
                        m1 = v;  j1 = i;
                    } else if (v > m2 || (v == m2 && i < j2)) {
                        m3 = m2; j3 = j2;
                        m2 = v;  j2 = i;
                    } else {
                        m3 = v;  j3 = i;
                    }
                }
            }
        }
        opc[(size_t)j0 * C] = 0.0f;
        opc[(size_t)j1 * C] = 0.0f;
        opc[(size_t)j2 * C] = 0.0f;
        opc[(size_t)j3 * C] = 0.0f;
    }
}

extern "C" void kernel_launch(void* const* d_in, const int* in_sizes, int n_in,
                              void* d_out, int out_size) {
    (void)in_sizes; (void)n_in; (void)out_size;
    const float* in  = (const float*)d_in[0];
    float*       out = (float*)d_out;
    numproto_topk_zero<<<GRID, BLK>>>(in, out);
}

// round 16
// speedup vs baseline: 1.0013x; 1.0013x over previous
#include <cuda_runtime.h>
#include <math_constants.h>

// contributions: [S=256, P=2000, C=200] fp32, row-major (c contiguous).
// Per (s, c) column along P: zero the top-4 (stable ties -> lower p), pass rest.
//
// R15 = R14 (best measured kernel time, 140.7us ncu) resubmitted at the
// established mixed-R/W DRAM ceiling (~5.57 TB/s across six independent
// designs). Block = one sample, 800 threads = 4 P-segments x 200 columns
// (zero idle threads), whole-800B-row streaming with __ldcs/__stcs, batched
// max-reject + short branchless insert, fused in-block smem merge with
// stable (value desc, index asc) tie-break, patch after __syncthreads().

static constexpr int S    = 256;
static constexpr int P    = 2000;
static constexpr int C    = 200;
static constexpr int SEG  = 4;                // P-segments per sample (in-block)
static constexpr int PSEG = P / SEG;          // 500
static constexpr int U    = 10;               // 500 = 50 * 10
static constexpr int NB   = PSEG / U;         // 50 batches
static constexpr int BLK  = SEG * C;          // 800 threads (25 warps)
static constexpr int GRID = S;                // 256 blocks

__global__ void __launch_bounds__(BLK, 2)
numproto_topk_zero(const float* __restrict__ in, float* __restrict__ out) {
    const int tid = threadIdx.x;
    const int s   = blockIdx.x;
    const int seg = tid / C;                  // 0..3
    const int c   = tid - seg * C;            // 0..199

    __shared__ float sv[SEG][4][C];
    __shared__ int   si[SEG][4][C];

    {
        const int p0 = seg * PSEG;
        const float* __restrict__ ipp = in  + (size_t)s * P * C + (size_t)p0 * C + c;
        float*       __restrict__ opp = out + (size_t)s * P * C + (size_t)p0 * C + c;

        float t0 = -CUDART_INF_F, t1 = -CUDART_INF_F,
              t2 = -CUDART_INF_F, t3 = -CUDART_INF_F;
        int   i0 = 0, i1 = 0, i2 = 0, i3 = 0;

        int pbase = p0;
        for (int it = 0; it < NB; it++) {
            float v[U];
            #pragma unroll
            for (int u = 0; u < U; u++)
                v[u] = __ldcs(ipp + u * C);   // streaming load, immediate offsets
            #pragma unroll
            for (int u = 0; u < U; u++)
                __stcs(opp + u * C, v[u]);    // streaming store

            // batch screen: one branch per 10 elements
            float m01 = fmaxf(v[0], v[1]);
            float m23 = fmaxf(v[2], v[3]);
            float m45 = fmaxf(v[4], v[5]);
            float m67 = fmaxf(v[6], v[7]);
            float m89 = fmaxf(v[8], v[9]);
            float mx  = fmaxf(fmaxf(fmaxf(m01, m23), fmaxf(m45, m67)), m89);

            if (mx > t3) {
                #pragma unroll
                for (int u = 0; u < U; u++) {
                    float vv = v[u];
                    if (vv > t3) {            // short branchless insert
                        const int pp = pbase + u;
                        const bool c0 = vv > t0;
                        const bool c1 = vv > t1;
                        const bool c2 = vv > t2;
                        float nt0 = c0 ? vv : t0;           int ni0 = c0 ? pp : i0;
                        float nt1 = c0 ? t0 : (c1 ? vv : t1);
                        int   ni1 = c0 ? i0 : (c1 ? pp : i1);
                        float nt2 = c1 ? t1 : (c2 ? vv : t2);
                        int   ni2 = c1 ? i1 : (c2 ? pp : i2);
                        float nt3 = c2 ? t2 : vv;           int ni3 = c2 ? i2 : pp;
                        t0 = nt0; t1 = nt1; t2 = nt2; t3 = nt3;
                        i0 = ni0; i1 = ni1; i2 = ni2; i3 = ni3;
                    }
                }
            }
            ipp += U * C;
            opp += U * C;
            pbase += U;
        }

        sv[seg][0][c] = t0;  si[seg][0][c] = i0;
        sv[seg][1][c] = t1;  si[seg][1][c] = i1;
        sv[seg][2][c] = t2;  si[seg][2][c] = i2;
        sv[seg][3][c] = t3;  si[seg][3][c] = i3;
    }

    __syncthreads();   // orders this block's copy-stores before the patch

    if (tid < C) {
        float* opc = out + (size_t)s * P * C + tid;

        float m0 = -CUDART_INF_F, m1 = -CUDART_INF_F,
              m2 = -CUDART_INF_F, m3 = -CUDART_INF_F;
        int   j0 = 0x7fffffff, j1 = 0x7fffffff,
              j2 = 0x7fffffff, j3 = 0x7fffffff;

        #pragma unroll
        for (int sg = 0; sg < SEG; sg++) {
            #pragma unroll
            for (int k = 0; k < 4; k++) {
                float v = sv[sg][k][tid];
                int   i = si[sg][k][tid];
                // stable order: value desc, index asc
                if (v > m3 || (v == m3 && i < j3)) {
                    if (v > m0 || (v == m0 && i < j0)) {
                        m3 = m2; j3 = j2; m2 = m1; j2 = j1; m1 = m0; j1 = j0;
                        m0 = v;  j0 = i;
                    } else if (v > m1 || (v == m1 && i < j1)) {
                        m3 = m2; j3 = j2; m2 = m1; j2 = j1;
                        m1 = v;  j1 = i;
                    } else if (v > m2 || (v == m2 && i < j2)) {
                        m3 = m2; j3 = j2;
                        m2 = v;  j2 = i;
                    } else {
                        m3 = v;  j3 = i;
                    }
                }
            }
        }
        opc[(size_t)j0 * C] = 0.0f;
        opc[(size_t)j1 * C] = 0.0f;
        opc[(size_t)j2 * C] = 0.0f;
        opc[(size_t)j3 * C] = 0.0f;
    }
}

extern "C" void kernel_launch(void* const* d_in, const int* in_sizes, int n_in,
                              void* d_out, int out_size) {
    (void)in_sizes; (void)n_in; (void)out_size;
    const float* in  = (const float*)d_in[0];
    float*       out = (float*)d_out;
    numproto_topk_zero<<<GRID, BLK>>>(in, out);
}